// round 16
// baseline (speedup 1.0000x reference)
#include <cuda_runtime.h>
#include <cuda_bf16.h>

#define NODES_MAX 50048
#define EMAX      2000000
#define D 128
#define SCAN_B 1024

// Scratch (alloc-free rule -> __device__ globals)
__device__ int g_idx_is_i64;
__device__ int g_deg[NODES_MAX];
__device__ int g_scan[NODES_MAX];        // per-block inclusive scans
__device__ int g_blk[64];                // block sums
__device__ int g_blk_exc[64];            // exclusive block offsets
__device__ int g_csr_off[NODES_MAX + 1];
__device__ int g_cursor[NODES_MAX];
__device__ int g_csr_src[EMAX];

__device__ __forceinline__ int load_idx(const void* p, int e) {
    return g_idx_is_i64 ? (int)((const long long*)p)[e] : ((const int*)p)[e];
}

// ---------------------------------------------------------------------------
// Kernel 1: zero degree counters; block 0 also detects index dtype.
// ---------------------------------------------------------------------------
__global__ void zero_detect_kernel(const void* __restrict__ src,
                                   int n, int n_edges) {
    int i = blockIdx.x * blockDim.x + threadIdx.x;
    if (i < n) g_deg[i] = 0;
    if (blockIdx.x == 0) {
        __shared__ int any_hi;
        if (threadIdx.x == 0) any_hi = 0;
        __syncthreads();
        int nsample = n_edges < 128 ? n_edges : 128;
        if (threadIdx.x < nsample) {
            int hi = ((const int*)src)[2 * threadIdx.x + 1];
            if (hi != 0) atomicOr(&any_hi, 1);
        }
        __syncthreads();
        if (threadIdx.x == 0) g_idx_is_i64 = any_hi ? 0 : 1;
    }
}

// ---------------------------------------------------------------------------
// CSR construction: histogram -> scan(x3) -> reorder  (measured-good chain)
// ---------------------------------------------------------------------------
__global__ void hist_kernel(const void* __restrict__ dst, int n_edges) {
    int e = blockIdx.x * blockDim.x + threadIdx.x;
    if (e >= n_edges) return;
    atomicAdd(&g_deg[load_idx(dst, e)], 1);
}

__global__ void scan1_kernel(int n) {
    __shared__ int s[SCAN_B];
    int t = threadIdx.x;
    int i = blockIdx.x * SCAN_B + t;
    int v = (i < n) ? g_deg[i] : 0;
    s[t] = v;
    __syncthreads();
    for (int o = 1; o < SCAN_B; o <<= 1) {
        int x = (t >= o) ? s[t - o] : 0;
        __syncthreads();
        s[t] += x;
        __syncthreads();
    }
    if (i < n) g_scan[i] = s[t];
    if (t == SCAN_B - 1) g_blk[blockIdx.x] = s[t];
}

__global__ void scan2_kernel(int nblk) {
    __shared__ int s[64];
    int t = threadIdx.x;
    int v = (t < nblk) ? g_blk[t] : 0;
    s[t] = v;
    __syncthreads();
    for (int o = 1; o < 64; o <<= 1) {
        int x = (t >= o) ? s[t - o] : 0;
        __syncthreads();
        s[t] += x;
        __syncthreads();
    }
    if (t < nblk) g_blk_exc[t] = s[t] - v;
}

__global__ void scan3_kernel(int n) {
    int i = blockIdx.x * blockDim.x + threadIdx.x;
    if (i >= n) return;
    int off = g_blk_exc[i / SCAN_B] + g_scan[i] - g_deg[i];
    g_csr_off[i] = off;
    g_cursor[i]  = off;
    if (i == n - 1) g_csr_off[n] = off + g_deg[i];
}

__global__ void reorder_kernel(const void* __restrict__ src,
                               const void* __restrict__ dst, int n_edges) {
    int e = blockIdx.x * blockDim.x + threadIdx.x;
    if (e >= n_edges) return;
    int d = load_idx(dst, e);
    int s = load_idx(src, e);
    int pos = atomicAdd(&g_cursor[d], 1);
    g_csr_src[pos] = s;
}

// ---------------------------------------------------------------------------
// FUSED kernel, warp-specialized producer/consumer, double-buffered hs.
//   1024 threads/CTA, 1 CTA/SM, 148 persistent blocks.
//   Warps 16..31 (producers): gather tile t into hs[t&1]   (LSU pipe)
//   Warps  0..15 (consumers): GEMM tile t-1 from hs[(t-1)&1] (FMA pipe)
//   __syncthreads() per iteration separates buffer reuse (distance 2).
// Gather/GEMM inner bodies identical to the measured 110.8us build.
// ---------------------------------------------------------------------------
#define TILE_M 64
#define WPAD 132
#define FUSED_BLOCKS 148

__global__ __launch_bounds__(1024, 1) void gin_fused_kernel(
    const float* __restrict__ feat, const float* __restrict__ W,
    const float* __restrict__ bias, const float* __restrict__ eps,
    float* __restrict__ out, int n_nodes) {
    extern __shared__ float sm[];
    float* Wt = sm;                        // [128][WPAD]
    float* hs0 = sm + D * WPAD;            // [TILE_M][128] buffer 0
    float* hs1 = hs0 + TILE_M * D;         // [TILE_M][128] buffer 1

    int tid  = threadIdx.x;
    int lane = tid & 31;
    int wid  = tid >> 5;                   // 0..31
    float s = 1.0f + eps[0];
    const float4* f4 = (const float4*)feat;

    // Stage W transposed once per block (all 1024 threads).
    for (int idx = tid; idx < D * D; idx += 1024) {
        int c = idx >> 7;
        int k = idx & 127;
        Wt[k * WPAD + c] = W[idx];
    }

    int n_tiles = (n_nodes + TILE_M - 1) / TILE_M;

    if (wid >= 16) {
        // ================= PRODUCER warps (16..31) =================
        int pw = wid - 16;                 // 0..15
        for (int it = 0; ; it++) {
            int cons_t = blockIdx.x + (it - 1) * (int)gridDim.x;
            if (cons_t >= n_tiles) break;
            __syncthreads();
            int prod_t = blockIdx.x + it * (int)gridDim.x;
            if (prod_t < n_tiles) {
                float* hs = (it & 1) ? hs1 : hs0;
                int m0 = prod_t * TILE_M;
                for (int r = pw; r < TILE_M; r += 16) {
                    int row = m0 + r;
                    float4 acc = make_float4(0.f, 0.f, 0.f, 0.f);
                    if (row < n_nodes) {
                        acc = f4[(size_t)row * 32 + lane];
                        acc.x *= s; acc.y *= s; acc.z *= s; acc.w *= s;
                        int j = g_csr_off[row], end = g_csr_off[row + 1];
                        for (; j + 1 < end; j += 2) {
                            int s0 = g_csr_src[j];
                            int s1 = g_csr_src[j + 1];
                            float4 v0 = f4[(size_t)s0 * 32 + lane];
                            float4 v1 = f4[(size_t)s1 * 32 + lane];
                            acc.x += v0.x + v1.x;
                            acc.y += v0.y + v1.y;
                            acc.z += v0.z + v1.z;
                            acc.w += v0.w + v1.w;
                        }
                        if (j < end) {
                            float4 v0 = f4[(size_t)g_csr_src[j] * 32 + lane];
                            acc.x += v0.x; acc.y += v0.y;
                            acc.z += v0.z; acc.w += v0.w;
                        }
                    }
                    ((float4*)(hs + r * D))[lane] = acc;
                }
            }
        }
    } else {
        // ================= CONSUMER warps (0..15) =================
        int tx = lane;                     // output cols 4*tx..4*tx+3
        int ty = wid;                      // rows 4*ty..4*ty+3
        float4 bv = *(const float4*)&bias[tx * 4];

        for (int it = 0; ; it++) {
            int cons_t = blockIdx.x + (it - 1) * (int)gridDim.x;
            if (cons_t >= n_tiles) break;
            __syncthreads();
            if (it == 0) continue;         // nothing produced yet
            float* hs = ((it - 1) & 1) ? hs1 : hs0;
            int m0 = cons_t * TILE_M;

            float acc[4][4];
#pragma unroll
            for (int i = 0; i < 4; i++)
#pragma unroll
                for (int j = 0; j < 4; j++) acc[i][j] = 0.f;

#pragma unroll 4
            for (int k = 0; k < D; k += 4) {
                float4 w0 = *(const float4*)&Wt[(k + 0) * WPAD + tx * 4];
                float4 w1 = *(const float4*)&Wt[(k + 1) * WPAD + tx * 4];
                float4 w2 = *(const float4*)&Wt[(k + 2) * WPAD + tx * 4];
                float4 w3 = *(const float4*)&Wt[(k + 3) * WPAD + tx * 4];
#pragma unroll
                for (int i = 0; i < 4; i++) {
                    float4 hv = *(const float4*)&hs[(ty * 4 + i) * D + k];
                    acc[i][0] += hv.x * w0.x + hv.y * w1.x + hv.z * w2.x + hv.w * w3.x;
                    acc[i][1] += hv.x * w0.y + hv.y * w1.y + hv.z * w2.y + hv.w * w3.y;
                    acc[i][2] += hv.x * w0.z + hv.y * w1.z + hv.z * w2.z + hv.w * w3.z;
                    acc[i][3] += hv.x * w0.w + hv.y * w1.w + hv.z * w2.w + hv.w * w3.w;
                }
            }

#pragma unroll
            for (int i = 0; i < 4; i++) {
                int row = m0 + ty * 4 + i;
                if (row < n_nodes) {
                    float4 o;
                    o.x = fmaxf(acc[i][0] + bv.x, 0.f);
                    o.y = fmaxf(acc[i][1] + bv.y, 0.f);
                    o.z = fmaxf(acc[i][2] + bv.z, 0.f);
                    o.w = fmaxf(acc[i][3] + bv.w, 0.f);
                    ((float4*)(out + (size_t)row * D))[tx] = o;
                }
            }
        }
    }
}

// ---------------------------------------------------------------------------
// Launch: zero+detect -> hist -> scan x3 -> reorder -> fused (pipelined).
// Graph-capturable, alloc-free.
// ---------------------------------------------------------------------------
extern "C" void kernel_launch(void* const* d_in, const int* in_sizes, int n_in,
                              void* d_out, int out_size) {
    const float* feature = (const float*)d_in[0];
    const void*  src     = d_in[1];
    const void*  dst     = d_in[2];
    const float* W       = (const float*)d_in[3];
    const float* bias    = (const float*)d_in[4];
    const float* eps     = (const float*)d_in[5];
    float*       out     = (float*)d_out;

    int n_nodes = in_sizes[0] / D;
    int n_edges = in_sizes[1];

    static bool smem_ok = false;
    size_t smem = (size_t)(D * WPAD + 2 * TILE_M * D) * sizeof(float); // ~130KB
    if (!smem_ok) {
        cudaFuncSetAttribute(gin_fused_kernel,
                             cudaFuncAttributeMaxDynamicSharedMemorySize,
                             (int)smem);
        smem_ok = true;
    }

    int nblk_scan = (n_nodes + SCAN_B - 1) / SCAN_B;  // 49 for 50k

    zero_detect_kernel<<<(n_nodes + 255) / 256, 256>>>(src, n_nodes, n_edges);
    hist_kernel<<<(n_edges + 255) / 256, 256>>>(dst, n_edges);
    scan1_kernel<<<nblk_scan, SCAN_B>>>(n_nodes);
    scan2_kernel<<<1, 64>>>(nblk_scan);
    scan3_kernel<<<(n_nodes + 255) / 256, 256>>>(n_nodes);
    reorder_kernel<<<(n_edges + 255) / 256, 256>>>(src, dst, n_edges);

    gin_fused_kernel<<<FUSED_BLOCKS, 1024, smem>>>(
        feature, W, bias, eps, out, n_nodes);
}